// round 16
// baseline (speedup 1.0000x reference)
#include <cuda_runtime.h>
#include <cstdint>

#define N_NODES 25000
#define N_EDGES 320000
#define F       64
#define NHEADS  5
#define NRELS   20
#define NBASES  10
#define OUTC    320
#define PSTRIDE 320          // padded per-node P row: 20 rels * 16
#define TOTC    584          // 64 z + 320 self_z + 200 P
#define WCOLS   640          // padded fused-W width
#define CHUNK   32
#define KW      32           // k-words per column (64 k / 2 per word)
#define SSTR    36           // smem row stride (words), conflict-free

// ---------------- static device scratch ------------------------------------
__device__ float    g_z [N_NODES * F];          // 6.4 MB
__device__ float    g_P [N_NODES * PSTRIDE];    // 32 MB padded
__device__ float    g_att[N_EDGES * 8];         // 10.2 MB per-edge att (pad 8)
__device__ uint32_t g_WbH[WCOLS * KW];          // fused W bf16x2 hi plane, [c][kw]
__device__ uint32_t g_WbL[WCOLS * KW];          // fused W bf16x2 lo plane
__device__ int      g_cnt [N_NODES];            // zero at load; self-restored by scan3
__device__ int      g_scan[N_NODES];
__device__ int      g_bsum[32];
__device__ int      g_cur [N_NODES];
__device__ unsigned g_srcrt[N_EDGES];           // src | rel<<16, sorted by dst
__device__ int      g_dstS [N_EDGES];           // dst, sorted

// ---------------- bf16 helpers ----------------------------------------------
__device__ __forceinline__ uint32_t bf16x2_rn(float x0, float x1) {
    uint32_t w;
    asm("cvt.rn.bf16x2.f32 %0, %1, %2;" : "=r"(w) : "f"(x1), "f"(x0));
    return w;
}
__device__ __forceinline__ void bf_split2(float x0, float x1, uint32_t& wh, uint32_t& wl) {
    wh = bf16x2_rn(x0, x1);
    float h0 = __uint_as_float(wh << 16);
    float h1 = __uint_as_float(wh & 0xFFFF0000u);
    wl = bf16x2_rn(x0 - h0, x1 - h1);
}
__device__ __forceinline__ void mma_bf16(float* d, const uint32_t* a, const uint32_t* b) {
    asm volatile("mma.sync.aligned.m16n8k16.row.col.f32.bf16.bf16.f32 "
                 "{%0,%1,%2,%3}, {%4,%5,%6,%7}, {%8,%9}, {%0,%1,%2,%3};"
                 : "+f"(d[0]), "+f"(d[1]), "+f"(d[2]), "+f"(d[3])
                 : "r"(a[0]), "r"(a[1]), "r"(a[2]), "r"(a[3]), "r"(b[0]), "r"(b[1]));
}

// ---------------------------------------------------------------------------
// attn_comp: basis composition + DIRECT bf16x2 pack of W cols 384..583.
// ---------------------------------------------------------------------------
__global__ void __launch_bounds__(320) attn_comp_kernel(const float* __restrict__ aw,
                                                        const float* __restrict__ w_comp,
                                                        const float* __restrict__ fc_w)
{
    __shared__ float afc[128 * NHEADS];
    const int r = blockIdx.x, tid = threadIdx.x;

    if (tid < 128) {
        float acc[NHEADS] = {};
#pragma unroll
        for (int b = 0; b < NBASES; b++) {
            float wc = w_comp[r * NBASES + b];
#pragma unroll
            for (int h = 0; h < NHEADS; h++)
                acc[h] += wc * aw[(b * 128 + tid) * NHEADS + h];
        }
#pragma unroll
        for (int h = 0; h < NHEADS; h++) afc[tid * NHEADS + h] = acc[h];
    }
    __syncthreads();

    const int kw = tid / 10;            // 0..31
    const int c2 = tid % 10;
    const int h  = c2 % 5;
    const float* af = afc + (c2 >= 5 ? 64 * NHEADS : 0) + h;
    const float* w0 = fc_w + (2 * kw) * 64;
    const float* w1 = fc_w + (2 * kw + 1) * 64;
    float s0 = 0.f, s1 = 0.f;
#pragma unroll
    for (int f = 0; f < 64; f++) {
        float a = af[f * NHEADS];
        s0 += w0[f] * a;
        s1 += w1[f] * a;
    }
    int col = 384 + (c2 >= 5 ? 100 : 0) + r * 5 + h;
    uint32_t wh, wl;
    bf_split2(s0, s1, wh, wl);
    g_WbH[col * KW + kw] = wh;
    g_WbL[col * KW + kw] = wl;
}

// ---------------------------------------------------------------------------
// split_w: W cols 0..383 (+ zero-pad >= 584) into packed bf16x2 planes.
// ---------------------------------------------------------------------------
__global__ void __launch_bounds__(256) split_w_kernel(const float* __restrict__ fc_w,
                                                      const float* __restrict__ self_fc_w)
{
    int t = blockIdx.x * 256 + threadIdx.x;
    if (t >= WCOLS * KW) return;
    int c = t >> 5, kw = t & 31;
    if (c >= 384 && c < TOTC) return;    // attn kernel owns these
    float x0 = 0.f, x1 = 0.f;
    if (c < 64) {
        x0 = fc_w[(2 * kw) * 64 + c];
        x1 = fc_w[(2 * kw + 1) * 64 + c];
    } else if (c < 384) {
        x0 = self_fc_w[(2 * kw) * 320 + (c - 64)];
        x1 = self_fc_w[(2 * kw + 1) * 320 + (c - 64)];
    }
    uint32_t wh, wl;
    bf_split2(x0, x1, wh, wl);
    g_WbH[t] = wh;
    g_WbL[t] = wl;
}

// ---------------------------------------------------------------------------
// Sort chain: hist(int4) -> scan1 -> scan3(+cnt reset) -> scatter(int4)
// ---------------------------------------------------------------------------
__global__ void hist_kernel(const int* __restrict__ dst)
{
    int t = blockIdx.x * blockDim.x + threadIdx.x;
    if (t < N_EDGES / 4) {
        int4 d = ((const int4*)dst)[t];
        atomicAdd(&g_cnt[d.x], 1); atomicAdd(&g_cnt[d.y], 1);
        atomicAdd(&g_cnt[d.z], 1); atomicAdd(&g_cnt[d.w], 1);
    }
}

__global__ void __launch_bounds__(1024) scan1_kernel()
{
    __shared__ int wsum[32];
    const int tid = threadIdx.x, lane = tid & 31, wid = tid >> 5;
    const int idx = blockIdx.x * 1024 + tid;
    int v = (idx < N_NODES) ? g_cnt[idx] : 0;
    int x = v;
#pragma unroll
    for (int d = 1; d < 32; d <<= 1) {
        int y = __shfl_up_sync(0xffffffffu, x, d);
        if (lane >= d) x += y;
    }
    if (lane == 31) wsum[wid] = x;
    __syncthreads();
    if (tid < 32) {
        int w = wsum[tid];
#pragma unroll
        for (int d = 1; d < 32; d <<= 1) {
            int y = __shfl_up_sync(0xffffffffu, w, d);
            if (tid >= d) w += y;
        }
        wsum[tid] = w;
    }
    __syncthreads();
    int incl = x + (wid > 0 ? wsum[wid - 1] : 0);
    if (idx < N_NODES) g_scan[idx] = incl;
    if (tid == 1023)   g_bsum[blockIdx.x] = incl;
}

__global__ void __launch_bounds__(1024) scan3_kernel()
{
    __shared__ int s_pre;
    const int tid = threadIdx.x;
    if (tid < 32) {
        int v = (tid < blockIdx.x) ? g_bsum[tid] : 0;
#pragma unroll
        for (int d = 16; d > 0; d >>= 1) v += __shfl_xor_sync(0xffffffffu, v, d);
        if (tid == 0) s_pre = v;
    }
    __syncthreads();
    int idx = blockIdx.x * 1024 + tid;
    if (idx < N_NODES) {
        int c = g_cnt[idx];
        g_cur[idx] = g_scan[idx] + s_pre - c;
        g_cnt[idx] = 0;                        // self-restore for next replay
    }
}

__global__ void scatter_kernel(const int* __restrict__ dst,
                               const int* __restrict__ src,
                               const int* __restrict__ et)
{
    int t = blockIdx.x * blockDim.x + threadIdx.x;
    if (t >= N_EDGES / 4) return;
    int4 d = ((const int4*)dst)[t];
    int4 s = ((const int4*)src)[t];
    int4 r = ((const int4*)et)[t];
    int dd[4] = {d.x, d.y, d.z, d.w};
    int ss[4] = {s.x, s.y, s.z, s.w};
    int rr[4] = {r.x, r.y, r.z, r.w};
#pragma unroll
    for (int j = 0; j < 4; j++) {
        int pos = atomicAdd(&g_cur[dd[j]], 1);
        g_srcrt[pos] = (unsigned)ss[j] | ((unsigned)rr[j] << 16);
        g_dstS[pos]  = dd[j];
    }
}

// ---------------------------------------------------------------------------
// proj_mma v7 (unchanged from r15; A frags in regs, 1 sync/chunk).
// ---------------------------------------------------------------------------
#define BUFW (2 * 64 * SSTR)
#define PROJ_SMEM (2 * BUFW * 4)

__global__ void __launch_bounds__(256, 3) proj_mma_kernel(const float* __restrict__ feat,
                                                          float* __restrict__ out)
{
    extern __shared__ uint32_t smem[];
    uint32_t* const buf0 = smem;
    uint32_t* const buf1 = smem + BUFW;

    const int tid = threadIdx.x;
    const int m0  = blockIdx.x * 64;
    const int bn  = tid >> 2;
    const int bkw = (tid & 3) * 8;

    uint4 h0, h1, l0, l1;
    {
        const uint4* ph = (const uint4*)(g_WbH) + tid * 2;
        const uint4* pl = (const uint4*)(g_WbL) + tid * 2;
        h0 = ph[0]; h1 = ph[1]; l0 = pl[0]; l1 = pl[1];
    }

    uint32_t* AsH = buf0;
    uint32_t* AsL = buf0 + 64 * SSTR;
#pragma unroll
    for (int i = 0; i < 4; i++) {
        int v = tid + i * 256;
        int row = v >> 4, s = v & 15;
        int node = m0 + row;
        float4 a = make_float4(0.f, 0.f, 0.f, 0.f);
        if (node < N_NODES) a = *(const float4*)(feat + node * F + 4 * s);
        uint32_t ah0, al0, ah1, al1;
        bf_split2(a.x, a.y, ah0, al0);
        bf_split2(a.z, a.w, ah1, al1);
        *(uint2*)(AsH + row * SSTR + 2 * s) = make_uint2(ah0, ah1);
        *(uint2*)(AsL + row * SSTR + 2 * s) = make_uint2(al0, al1);
    }
    __syncthreads();

    const int wid  = tid >> 5;
    const int lane = tid & 31;
    const int gid  = lane >> 2;
    const int tig  = lane & 3;
    const int wrow = wid & 3;
    const int wcol = (wid >> 2) * 32;
    const int rb   = 16 * wrow + gid;
    const int r0   = m0 + rb;

    uint32_t ahr[4][4], alr[4][4];
    {
        const uint32_t* aH0 = AsH + rb * SSTR + tig;
        const uint32_t* aH1 = AsH + (rb + 8) * SSTR + tig;
        const uint32_t* aL0 = AsL + rb * SSTR + tig;
        const uint32_t* aL1 = AsL + (rb + 8) * SSTR + tig;
#pragma unroll
        for (int ks = 0; ks < 4; ks++) {
            const int kb = 8 * ks;
            ahr[ks][0] = aH0[kb];     ahr[ks][1] = aH1[kb];
            ahr[ks][2] = aH0[kb + 4]; ahr[ks][3] = aH1[kb + 4];
            alr[ks][0] = aL0[kb];     alr[ks][1] = aL1[kb];
            alr[ks][2] = aL0[kb + 4]; alr[ks][3] = aL1[kb + 4];
        }
    }

    *(uint4*)(buf1 + bn * SSTR + bkw)              = h0;
    *(uint4*)(buf1 + bn * SSTR + bkw + 4)          = h1;
    *(uint4*)(buf1 + 64 * SSTR + bn * SSTR + bkw)     = l0;
    *(uint4*)(buf1 + 64 * SSTR + bn * SSTR + bkw + 4) = l1;
    {
        const uint4* ph = (const uint4*)(g_WbH + 64 * KW) + tid * 2;
        const uint4* pl = (const uint4*)(g_WbL + 64 * KW) + tid * 2;
        h0 = ph[0]; h1 = ph[1]; l0 = pl[0]; l1 = pl[1];
    }
    __syncthreads();

#pragma unroll 1
    for (int i = 0; i < 10; i++) {
        const int c0 = i * 64;
        uint32_t* cur  = (i & 1) ? buf0 : buf1;
        uint32_t* curH = cur;
        uint32_t* curL = cur + 64 * SSTR;

        float d[4][4];
#pragma unroll
        for (int j = 0; j < 4; j++)
#pragma unroll
            for (int q = 0; q < 4; q++) d[j][q] = 0.f;

#pragma unroll
        for (int ks = 0; ks < 4; ks++) {
            const int kb = 8 * ks;
#pragma unroll
            for (int j = 0; j < 4; j++) {
                const uint32_t* bh = curH + (wcol + 8 * j + gid) * SSTR + tig;
                const uint32_t* bl = curL + (wcol + 8 * j + gid) * SSTR + tig;
                uint32_t bhf[2], blf[2];
                bhf[0] = bh[kb]; bhf[1] = bh[kb + 4];
                blf[0] = bl[kb]; blf[1] = bl[kb + 4];
                mma_bf16(d[j], ahr[ks], bhf);
                mma_bf16(d[j], alr[ks], bhf);
                mma_bf16(d[j], ahr[ks], blf);
            }
        }

        if (i + 1 < 10) {
            uint32_t* nb = (i & 1) ? buf1 : buf0;
            *(uint4*)(nb + bn * SSTR + bkw)              = h0;
            *(uint4*)(nb + bn * SSTR + bkw + 4)          = h1;
            *(uint4*)(nb + 64 * SSTR + bn * SSTR + bkw)     = l0;
            *(uint4*)(nb + 64 * SSTR + bn * SSTR + bkw + 4) = l1;
            if (i + 2 < 10) {
                const uint4* ph = (const uint4*)(g_WbH + (i + 2) * 64 * KW) + tid * 2;
                const uint4* pl = (const uint4*)(g_WbL + (i + 2) * 64 * KW) + tid * 2;
                h0 = ph[0]; h1 = ph[1]; l0 = pl[0]; l1 = pl[1];
            }
        }

        const int cb = tig * 2;
#pragma unroll
        for (int j = 0; j < 4; j++) {
            int gc = c0 + wcol + 8 * j + cb;
            if (gc >= TOTC) continue;
#pragma unroll
            for (int half = 0; half < 2; half++) {
                int node = r0 + 8 * half;
                if (node >= N_NODES) continue;
                float x = d[j][2 * half], y = d[j][2 * half + 1];
                if (gc < 64) {
                    *(float2*)(g_z + node * F + gc) = make_float2(x, y);
                } else if (gc < 384) {
                    *(float2*)(out + node * OUTC + (gc - 64)) = make_float2(x, y);
                } else {
#pragma unroll
                    for (int t = 0; t < 2; t++) {
                        int ix = gc - 384 + t;
                        int part = (ix >= 100) ? 8 : 0;
                        int pix  = (ix >= 100) ? ix - 100 : ix;
                        int rr = pix / 5, hh = pix % 5;
                        g_P[node * PSTRIDE + rr * 16 + part + hh] = t ? y : x;
                    }
                }
            }
        }
        __syncthreads();
    }
}

// ---------------------------------------------------------------------------
// att_kernel: edge-parallel attention. One thread per sorted edge; massive
// thread-level parallelism hides the P-gather latency.
// ---------------------------------------------------------------------------
__global__ void __launch_bounds__(256) att_kernel()
{
    int e = blockIdx.x * 256 + threadIdx.x;
    if (e >= N_EDGES) return;
    unsigned pk = g_srcrt[e];
    int d = g_dstS[e];
    int s = pk & 0xFFFFu, r = pk >> 16;
    const float* pp = g_P + s * PSTRIDE + r * 16;
    const float* qq = g_P + d * PSTRIDE + r * 16 + 8;
    float4 ps4 = *(const float4*)pp;  float ps1 = pp[4];
    float4 pd4 = *(const float4*)qq;  float pd1 = qq[4];
    float a0 = ps4.x + pd4.x;  a0 = a0 > 0.f ? a0 : 0.01f * a0;
    float a1 = ps4.y + pd4.y;  a1 = a1 > 0.f ? a1 : 0.01f * a1;
    float a2 = ps4.z + pd4.z;  a2 = a2 > 0.f ? a2 : 0.01f * a2;
    float a3 = ps4.w + pd4.w;  a3 = a3 > 0.f ? a3 : 0.01f * a3;
    float a4 = ps1   + pd1;    a4 = a4 > 0.f ? a4 : 0.01f * a4;
    *(float4*)(g_att + e * 8) = make_float4(a0, a1, a2, a3);
    g_att[e * 8 + 4] = a4;
}

// ---------------------------------------------------------------------------
// gather v3: slim loop — att precomputed; 3 loads/edge; red.v2 flushes.
// ---------------------------------------------------------------------------
__global__ void __launch_bounds__(256) gather_kernel(float* __restrict__ out)
{
    const int w = threadIdx.x >> 5, lane = threadIdx.x & 31;
    const int gw = blockIdx.x * 8 + w;
    const int e0 = gw * CHUNK;
    if (e0 >= N_EDGES) return;

    const unsigned pk_all = g_srcrt[e0 + lane];
    const int      dd_all = g_dstS [e0 + lane];

    float acc[10];
#pragma unroll
    for (int q = 0; q < 10; q++) acc[q] = 0.f;

    unsigned pk = __shfl_sync(0xffffffffu, pk_all, 0);
    int d_n = __shfl_sync(0xffffffffu, dd_all, 0);
    int s0 = pk & 0xFFFFu;
    float2 zs_n = *(const float2*)(g_z + s0 * F + 2 * lane);
    float4 at4_n = *(const float4*)(g_att + (long)e0 * 8);
    float  at1_n = g_att[(long)e0 * 8 + 4];
    int d_cur = d_n;

#pragma unroll 4
    for (int i = 0; i < CHUNK; i++) {
        const int    d_c = d_n;
        const float2 zs  = zs_n;
        const float4 a4  = at4_n;
        const float  a1v = at1_n;

        if (i + 1 < CHUNK) {
            unsigned pk2 = __shfl_sync(0xffffffffu, pk_all, i + 1);
            d_n = __shfl_sync(0xffffffffu, dd_all, i + 1);
            int s2 = pk2 & 0xFFFFu;
            zs_n = *(const float2*)(g_z + s2 * F + 2 * lane);
            at4_n = *(const float4*)(g_att + (long)(e0 + i + 1) * 8);
            at1_n = g_att[(long)(e0 + i + 1) * 8 + 4];
        }

        if (d_c != d_cur) {   // warp-uniform: flush accumulator
            float* ob = out + (long)d_cur * OUTC + 2 * lane;
#pragma unroll
            for (int h = 0; h < NHEADS; h++)
                asm volatile("red.global.add.v2.f32 [%0], {%1, %2};"
                             :: "l"(ob + h * F), "f"(acc[2 * h]), "f"(acc[2 * h + 1])
                             : "memory");
#pragma unroll
            for (int q = 0; q < 10; q++) acc[q] = 0.f;
            d_cur = d_c;
        }

        acc[0] += a4.x * zs.x;  acc[1] += a4.x * zs.y;
        acc[2] += a4.y * zs.x;  acc[3] += a4.y * zs.y;
        acc[4] += a4.z * zs.x;  acc[5] += a4.z * zs.y;
        acc[6] += a4.w * zs.x;  acc[7] += a4.w * zs.y;
        acc[8] += a1v * zs.x;   acc[9] += a1v * zs.y;
    }

    float* ob = out + (long)d_cur * OUTC + 2 * lane;
#pragma unroll
    for (int h = 0; h < NHEADS; h++)
        asm volatile("red.global.add.v2.f32 [%0], {%1, %2};"
                     :: "l"(ob + h * F), "f"(acc[2 * h]), "f"(acc[2 * h + 1])
                     : "memory");
}

// ---------------------------------------------------------------------------
extern "C" void kernel_launch(void* const* d_in, const int* in_sizes, int n_in,
                              void* d_out, int out_size)
{
    const float* feat      = (const float*)d_in[0];
    const int*   src       = (const int*)  d_in[1];
    const int*   dst       = (const int*)  d_in[2];
    const int*   etype     = (const int*)  d_in[3];
    const float* fc_w      = (const float*)d_in[4];
    const float* self_fc_w = (const float*)d_in[5];
    const float* aw        = (const float*)d_in[6];
    const float* w_comp    = (const float*)d_in[7];
    float* out = (float*)d_out;

    const int NB = (N_NODES + 1023) / 1024;   // 25

    static cudaStream_t s_side = nullptr;
    static cudaEvent_t  ev_fork = nullptr, ev_sort = nullptr;
    if (s_side == nullptr) {
        cudaStreamCreateWithFlags(&s_side, cudaStreamNonBlocking);
        cudaEventCreateWithFlags(&ev_fork, cudaEventDisableTiming);
        cudaEventCreateWithFlags(&ev_sort, cudaEventDisableTiming);
        cudaFuncSetAttribute(proj_mma_kernel,
                             cudaFuncAttributeMaxDynamicSharedMemorySize, PROJ_SMEM);
    }

    // ---- fork: sort chain on side stream
    cudaEventRecord(ev_fork, 0);
    cudaStreamWaitEvent(s_side, ev_fork, 0);
    hist_kernel<<<(N_EDGES / 4 + 255) / 256, 256, 0, s_side>>>(dst);     // launch 1

    // ---- main stream: weights -> projection GEMM (proj is 4th launch -> profiled)
    split_w_kernel<<<(WCOLS * KW + 255) / 256, 256>>>(fc_w, self_fc_w);  // launch 2
    attn_comp_kernel<<<NRELS, 320>>>(aw, w_comp, fc_w);                  // launch 3
    proj_mma_kernel<<<(N_NODES + 63) / 64, 256, PROJ_SMEM>>>(feat, out); // launch 4

    // ---- side stream: rest of sort chain
    scan1_kernel<<<NB, 1024, 0, s_side>>>();                             // launch 5
    scan3_kernel<<<NB, 1024, 0, s_side>>>();                             // launch 6
    scatter_kernel<<<(N_EDGES / 4 + 255) / 256, 256, 0, s_side>>>(dst, src, etype); // 7
    cudaEventRecord(ev_sort, s_side);

    // ---- join, then att + gather
    cudaStreamWaitEvent(0, ev_sort, 0);
    att_kernel<<<(N_EDGES + 255) / 256, 256>>>();                        // launch 8
    gather_kernel<<<(N_EDGES / CHUNK + 7) / 8, 256>>>(out);              // launch 9
}

// round 17
// speedup vs baseline: 1.0356x; 1.0356x over previous
#include <cuda_runtime.h>
#include <cstdint>

#define N_NODES 25000
#define N_EDGES 320000
#define F       64
#define NHEADS  5
#define NRELS   20
#define NBASES  10
#define OUTC    320
#define PSTRIDE 320          // padded per-node P row: 20 rels * 16
#define TOTC    704          // 64 z + 320 self_z + 320 P(padded layout)
#define WCOLS   704          // fused-W width (11 chunks of 64)
#define CHUNK   16
#define KW      32           // k-words per column (64 k / 2 per word)
#define SSTR    36           // smem row stride (words), conflict-free

// ---------------- static device scratch ------------------------------------
__device__ float    g_z [N_NODES * F];          // 6.4 MB
__device__ float    g_P [N_NODES * PSTRIDE];    // 32 MB padded: [n][r*16 + (s:0..4 | d:8..12)]
__device__ uint32_t g_WbH[WCOLS * KW];          // fused W bf16x2 hi plane, [c][kw]
__device__ uint32_t g_WbL[WCOLS * KW];          // fused W bf16x2 lo plane
__device__ int      g_cnt [N_NODES];            // zero at load; self-restored by scan3
__device__ int      g_scan[N_NODES];
__device__ int      g_bsum[32];
__device__ int      g_cur [N_NODES];
__device__ unsigned g_srcrt[N_EDGES];           // src | rel<<16, sorted by dst
__device__ int      g_dstS [N_EDGES];           // dst, sorted

// ---------------- helpers ----------------------------------------------------
__device__ __forceinline__ uint32_t s2u(const void* p) {
    return (uint32_t)__cvta_generic_to_shared(p);
}
#define CP16(dst, src)  asm volatile("cp.async.ca.shared.global [%0], [%1], 16;" :: "r"(dst), "l"(src))
#define CP_COMMIT()     asm volatile("cp.async.commit_group;" ::: "memory")

__device__ __forceinline__ uint32_t bf16x2_rn(float x0, float x1) {
    uint32_t w;
    asm("cvt.rn.bf16x2.f32 %0, %1, %2;" : "=r"(w) : "f"(x1), "f"(x0));
    return w;
}
__device__ __forceinline__ void bf_split2(float x0, float x1, uint32_t& wh, uint32_t& wl) {
    wh = bf16x2_rn(x0, x1);
    float h0 = __uint_as_float(wh << 16);
    float h1 = __uint_as_float(wh & 0xFFFF0000u);
    wl = bf16x2_rn(x0 - h0, x1 - h1);
}
__device__ __forceinline__ void mma_bf16(float* d, const uint32_t* a, const uint32_t* b) {
    asm volatile("mma.sync.aligned.m16n8k16.row.col.f32.bf16.bf16.f32 "
                 "{%0,%1,%2,%3}, {%4,%5,%6,%7}, {%8,%9}, {%0,%1,%2,%3};"
                 : "+f"(d[0]), "+f"(d[1]), "+f"(d[2]), "+f"(d[3])
                 : "r"(a[0]), "r"(a[1]), "r"(a[2]), "r"(a[3]), "r"(b[0]), "r"(b[1]));
}

// ---------------------------------------------------------------------------
// attn_comp: basis composition + DIRECT bf16x2 pack of W cols 384..703
// (padded layout: col = 384 + r*16 + (s: h | d: 8+h)).
// ---------------------------------------------------------------------------
__global__ void __launch_bounds__(320) attn_comp_kernel(const float* __restrict__ aw,
                                                        const float* __restrict__ w_comp,
                                                        const float* __restrict__ fc_w)
{
    __shared__ float afc[128 * NHEADS];
    const int r = blockIdx.x, tid = threadIdx.x;

    if (tid < 128) {
        float acc[NHEADS] = {};
#pragma unroll
        for (int b = 0; b < NBASES; b++) {
            float wc = w_comp[r * NBASES + b];
#pragma unroll
            for (int h = 0; h < NHEADS; h++)
                acc[h] += wc * aw[(b * 128 + tid) * NHEADS + h];
        }
#pragma unroll
        for (int h = 0; h < NHEADS; h++) afc[tid * NHEADS + h] = acc[h];
    }
    __syncthreads();

    const int kw = tid / 10;            // 0..31
    const int c2 = tid % 10;
    const int h  = c2 % 5;
    const float* af = afc + (c2 >= 5 ? 64 * NHEADS : 0) + h;
    const float* w0 = fc_w + (2 * kw) * 64;
    const float* w1 = fc_w + (2 * kw + 1) * 64;
    float s0 = 0.f, s1 = 0.f;
#pragma unroll
    for (int f = 0; f < 64; f++) {
        float a = af[f * NHEADS];
        s0 += w0[f] * a;
        s1 += w1[f] * a;
    }
    int col = 384 + r * 16 + (c2 >= 5 ? 8 : 0) + h;
    uint32_t wh, wl;
    bf_split2(s0, s1, wh, wl);
    g_WbH[col * KW + kw] = wh;
    g_WbL[col * KW + kw] = wl;
}

// ---------------------------------------------------------------------------
// split_w: W cols 0..383 + zero pad cols in 384..703 not owned by attn_comp.
// ---------------------------------------------------------------------------
__global__ void __launch_bounds__(256) split_w_kernel(const float* __restrict__ fc_w,
                                                      const float* __restrict__ self_fc_w)
{
    int t = blockIdx.x * 256 + threadIdx.x;
    if (t >= WCOLS * KW) return;
    int c = t >> 5, kw = t & 31;
    float x0 = 0.f, x1 = 0.f;
    if (c < 64) {
        x0 = fc_w[(2 * kw) * 64 + c];
        x1 = fc_w[(2 * kw + 1) * 64 + c];
    } else if (c < 384) {
        x0 = self_fc_w[(2 * kw) * 320 + (c - 64)];
        x1 = self_fc_w[(2 * kw + 1) * 320 + (c - 64)];
    } else {
        int off = (c - 384) & 15;
        if (off < 5 || (off >= 8 && off < 13)) return;   // attn_comp owns
    }
    uint32_t wh, wl;
    bf_split2(x0, x1, wh, wl);
    g_WbH[t] = wh;
    g_WbL[t] = wl;
}

// ---------------------------------------------------------------------------
// Sort chain: hist(int4) -> scan1 -> scan3(+cnt reset) -> scatter(int4)
// ---------------------------------------------------------------------------
__global__ void hist_kernel(const int* __restrict__ dst)
{
    int t = blockIdx.x * blockDim.x + threadIdx.x;
    if (t < N_EDGES / 4) {
        int4 d = ((const int4*)dst)[t];
        atomicAdd(&g_cnt[d.x], 1); atomicAdd(&g_cnt[d.y], 1);
        atomicAdd(&g_cnt[d.z], 1); atomicAdd(&g_cnt[d.w], 1);
    }
}

__global__ void __launch_bounds__(1024) scan1_kernel()
{
    __shared__ int wsum[32];
    const int tid = threadIdx.x, lane = tid & 31, wid = tid >> 5;
    const int idx = blockIdx.x * 1024 + tid;
    int v = (idx < N_NODES) ? g_cnt[idx] : 0;
    int x = v;
#pragma unroll
    for (int d = 1; d < 32; d <<= 1) {
        int y = __shfl_up_sync(0xffffffffu, x, d);
        if (lane >= d) x += y;
    }
    if (lane == 31) wsum[wid] = x;
    __syncthreads();
    if (tid < 32) {
        int w = wsum[tid];
#pragma unroll
        for (int d = 1; d < 32; d <<= 1) {
            int y = __shfl_up_sync(0xffffffffu, w, d);
            if (tid >= d) w += y;
        }
        wsum[tid] = w;
    }
    __syncthreads();
    int incl = x + (wid > 0 ? wsum[wid - 1] : 0);
    if (idx < N_NODES) g_scan[idx] = incl;
    if (tid == 1023)   g_bsum[blockIdx.x] = incl;
}

__global__ void __launch_bounds__(1024) scan3_kernel()
{
    __shared__ int s_pre;
    const int tid = threadIdx.x;
    if (tid < 32) {
        int v = (tid < blockIdx.x) ? g_bsum[tid] : 0;
#pragma unroll
        for (int d = 16; d > 0; d >>= 1) v += __shfl_xor_sync(0xffffffffu, v, d);
        if (tid == 0) s_pre = v;
    }
    __syncthreads();
    int idx = blockIdx.x * 1024 + tid;
    if (idx < N_NODES) {
        int c = g_cnt[idx];
        g_cur[idx] = g_scan[idx] + s_pre - c;
        g_cnt[idx] = 0;                        // self-restore for next replay
    }
}

__global__ void scatter_kernel(const int* __restrict__ dst,
                               const int* __restrict__ src,
                               const int* __restrict__ et)
{
    int t = blockIdx.x * blockDim.x + threadIdx.x;
    if (t >= N_EDGES / 4) return;
    int4 d = ((const int4*)dst)[t];
    int4 s = ((const int4*)src)[t];
    int4 r = ((const int4*)et)[t];
    int dd[4] = {d.x, d.y, d.z, d.w};
    int ss[4] = {s.x, s.y, s.z, s.w};
    int rr[4] = {r.x, r.y, r.z, r.w};
#pragma unroll
    for (int j = 0; j < 4; j++) {
        int pos = atomicAdd(&g_cur[dd[j]], 1);
        g_srcrt[pos] = (unsigned)ss[j] | ((unsigned)rr[j] << 16);
        g_dstS[pos]  = dd[j];
    }
}

// ---------------------------------------------------------------------------
// proj_mma v8: 32-row blocks (grid 782), 256 thr, 4 blocks/SM.
// B double-buffered via cp.async (depth 2); A frags in registers; epilogue
// writes g_P directly (padded W layout, no div/mod).
// smem: 2 buffers x (H+L planes [64][36]w) = 36.9 KB.
// ---------------------------------------------------------------------------
#define BUFW (2 * 64 * SSTR)
#define PROJ_SMEM (2 * BUFW * 4)

__global__ void __launch_bounds__(256, 4) proj_mma_kernel(const float* __restrict__ feat,
                                                          float* __restrict__ out)
{
    extern __shared__ uint32_t smem[];
    uint32_t* const buf0 = smem;
    uint32_t* const buf1 = smem + BUFW;

    const int tid = threadIdx.x;
    const int m0  = blockIdx.x * 32;
    const int bn  = tid >> 2;                // B-copy col 0..63
    const int bkw = (tid & 3) * 8;           // B-copy kw base

    const uint32_t dH0 = s2u(buf0 + bn * SSTR + bkw);
    const uint32_t dL0 = s2u(buf0 + 64 * SSTR + bn * SSTR + bkw);
    const uint32_t dH1 = s2u(buf1 + bn * SSTR + bkw);
    const uint32_t dL1 = s2u(buf1 + 64 * SSTR + bn * SSTR + bkw);

    // ---- cp.async chunk 0 -> buf1 (independent of A split)
    {
        const uint32_t* sH = g_WbH + bn * KW + bkw;
        const uint32_t* sL = g_WbL + bn * KW + bkw;
        CP16(dH1, sH); CP16(dH1 + 16, sH + 4);
        CP16(dL1, sL); CP16(dL1 + 16, sL + 4);
        CP_COMMIT();
    }

    // ---- A tile (32 x 64): load feat + bf16-split into buf0
    uint32_t* AsH = buf0;
    uint32_t* AsL = buf0 + 32 * SSTR;
#pragma unroll
    for (int i = 0; i < 2; i++) {
        int v = tid + i * 256;                 // 0..511 float4 slots
        int row = v >> 4, s = v & 15;
        int node = m0 + row;
        float4 a = make_float4(0.f, 0.f, 0.f, 0.f);
        if (node < N_NODES) a = *(const float4*)(feat + node * F + 4 * s);
        uint32_t ah0, al0, ah1, al1;
        bf_split2(a.x, a.y, ah0, al0);
        bf_split2(a.z, a.w, ah1, al1);
        *(uint2*)(AsH + row * SSTR + 2 * s) = make_uint2(ah0, ah1);
        *(uint2*)(AsL + row * SSTR + 2 * s) = make_uint2(al0, al1);
    }
    __syncthreads();

    const int wid  = tid >> 5;
    const int lane = tid & 31;
    const int gid  = lane >> 2;
    const int tig  = lane & 3;
    const int wrow = wid & 1;                // 2 row groups of 16
    const int wcol = (wid >> 1) * 16;        // 4 col groups of 16
    const int rb   = 16 * wrow + gid;
    const int r0   = m0 + rb;

    // ---- hoist A fragments into registers (chunk-invariant)
    uint32_t ahr[4][4], alr[4][4];
    {
        const uint32_t* aH0 = AsH + rb * SSTR + tig;
        const uint32_t* aH1 = AsH + (rb + 8) * SSTR + tig;
        const uint32_t* aL0 = AsL + rb * SSTR + tig;
        const uint32_t* aL1 = AsL + (rb + 8) * SSTR + tig;
#pragma unroll
        for (int ks = 0; ks < 4; ks++) {
            const int kb = 8 * ks;
            ahr[ks][0] = aH0[kb];     ahr[ks][1] = aH1[kb];
            ahr[ks][2] = aH0[kb + 4]; ahr[ks][3] = aH1[kb + 4];
            alr[ks][0] = aL0[kb];     alr[ks][1] = aL1[kb];
            alr[ks][2] = aL0[kb + 4]; alr[ks][3] = aL1[kb + 4];
        }
    }
    __syncthreads();   // everyone done reading buf0 (A planes)

    // ---- cp.async chunk 1 -> buf0
    {
        const uint32_t* sH = g_WbH + (64 + bn) * KW + bkw;
        const uint32_t* sL = g_WbL + (64 + bn) * KW + bkw;
        CP16(dH0, sH); CP16(dH0 + 16, sH + 4);
        CP16(dL0, sL); CP16(dL0 + 16, sL + 4);
        CP_COMMIT();
    }

#pragma unroll 1
    for (int i = 0; i < 11; i++) {
        const int c0 = i * 64;
        uint32_t* cur = (i & 1) ? buf0 : buf1;   // chunk i lives in buf[(i+1)&1]

        if (i < 10) asm volatile("cp.async.wait_group 1;" ::: "memory");
        else        asm volatile("cp.async.wait_group 0;" ::: "memory");
        __syncthreads();   // all threads' copies for chunk i visible

        float d[2][4];
#pragma unroll
        for (int j = 0; j < 2; j++)
#pragma unroll
            for (int q = 0; q < 4; q++) d[j][q] = 0.f;

#pragma unroll
        for (int ks = 0; ks < 4; ks++) {
            const int kb = 8 * ks;
#pragma unroll
            for (int j = 0; j < 2; j++) {
                const uint32_t* bh = cur + (wcol + 8 * j + gid) * SSTR + tig;
                const uint32_t* bl = bh + 64 * SSTR;
                uint32_t bhf[2], blf[2];
                bhf[0] = bh[kb]; bhf[1] = bh[kb + 4];
                blf[0] = bl[kb]; blf[1] = bl[kb + 4];
                mma_bf16(d[j], ahr[ks], bhf);
                mma_bf16(d[j], alr[ks], bhf);
                mma_bf16(d[j], ahr[ks], blf);
            }
        }
        __syncthreads();   // all warps done reading cur

        // ---- issue copy of chunk i+2 into cur (overlaps epilogue)
        if (i + 2 < 11) {
            uint32_t dH = (i & 1) ? dH0 : dH1;
            uint32_t dL = (i & 1) ? dL0 : dL1;
            const uint32_t* sH = g_WbH + ((i + 2) * 64 + bn) * KW + bkw;
            const uint32_t* sL = g_WbL + ((i + 2) * 64 + bn) * KW + bkw;
            CP16(dH, sH); CP16(dH + 16, sH + 4);
            CP16(dL, sL); CP16(dL + 16, sL + 4);
            CP_COMMIT();
        }

        // ---- epilogue: route to g_z / out / g_P (direct layout)
        const int cb = tig * 2;
#pragma unroll
        for (int j = 0; j < 2; j++) {
            int gc = c0 + wcol + 8 * j + cb;
#pragma unroll
            for (int half = 0; half < 2; half++) {
                int node = r0 + 8 * half;
                if (node >= N_NODES) continue;
                float x = d[j][2 * half], y = d[j][2 * half + 1];
                if (gc < 64)
                    *(float2*)(g_z + node * F + gc) = make_float2(x, y);
                else if (gc < 384)
                    *(float2*)(out + node * OUTC + (gc - 64)) = make_float2(x, y);
                else
                    *(float2*)(g_P + node * PSTRIDE + (gc - 384)) = make_float2(x, y);
            }
        }
    }
}

// ---------------------------------------------------------------------------
// gather (r15 v2, CHUNK=16): lane-distributed index prefetch + red.v2 flushes.
// ---------------------------------------------------------------------------
__global__ void __launch_bounds__(256) gather_kernel(float* __restrict__ out)
{
    const int w = threadIdx.x >> 5, lane = threadIdx.x & 31;
    const int gw = blockIdx.x * 8 + w;
    const int e0 = gw * CHUNK;
    if (e0 >= N_EDGES) return;

    int el = e0 + lane;
    if (el >= N_EDGES) el = N_EDGES - 1;
    const unsigned pk_all = g_srcrt[el];
    const int      dd_all = g_dstS [el];

    float acc[10];
#pragma unroll
    for (int q = 0; q < 10; q++) acc[q] = 0.f;

    unsigned pk = __shfl_sync(0xffffffffu, pk_all, 0);
    int d_n = __shfl_sync(0xffffffffu, dd_all, 0);
    int s0 = pk & 0xFFFFu, rr0 = pk >> 16;
    float2 zs_n = *(const float2*)(g_z + s0 * F + 2 * lane);
    const float* pp = g_P + s0 * PSTRIDE + rr0 * 16;
    const float* qq = g_P + d_n * PSTRIDE + rr0 * 16 + 8;
    float4 ps4_n = *(const float4*)pp;  float ps1_n = pp[4];
    float4 pd4_n = *(const float4*)qq;  float pd1_n = qq[4];
    int d_cur = d_n;

#pragma unroll 4
    for (int i = 0; i < CHUNK; i++) {
        const int    d_c  = d_n;
        const float2 zs   = zs_n;
        const float4 ps4  = ps4_n, pd4 = pd4_n;
        const float  ps1  = ps1_n, pd1 = pd1_n;

        if (i + 1 < CHUNK) {
            unsigned pk2 = __shfl_sync(0xffffffffu, pk_all, i + 1);
            d_n = __shfl_sync(0xffffffffu, dd_all, i + 1);
            int s2 = pk2 & 0xFFFFu, r2 = pk2 >> 16;
            zs_n = *(const float2*)(g_z + s2 * F + 2 * lane);
            const float* p2 = g_P + s2 * PSTRIDE + r2 * 16;
            const float* p3 = g_P + d_n * PSTRIDE + r2 * 16 + 8;
            ps4_n = *(const float4*)p2;  ps1_n = p2[4];
            pd4_n = *(const float4*)p3;  pd1_n = p3[4];
        }

        if (d_c != d_cur) {   // warp-uniform: flush accumulator
            float* ob = out + (long)d_cur * OUTC + 2 * lane;
#pragma unroll
            for (int h = 0; h < NHEADS; h++)
                asm volatile("red.global.add.v2.f32 [%0], {%1, %2};"
                             :: "l"(ob + h * F), "f"(acc[2 * h]), "f"(acc[2 * h + 1])
                             : "memory");
#pragma unroll
            for (int q = 0; q < 10; q++) acc[q] = 0.f;
            d_cur = d_c;
        }

        float a0 = ps4.x + pd4.x;  a0 = a0 > 0.f ? a0 : 0.01f * a0;
        float a1 = ps4.y + pd4.y;  a1 = a1 > 0.f ? a1 : 0.01f * a1;
        float a2 = ps4.z + pd4.z;  a2 = a2 > 0.f ? a2 : 0.01f * a2;
        float a3 = ps4.w + pd4.w;  a3 = a3 > 0.f ? a3 : 0.01f * a3;
        float a4 = ps1   + pd1;    a4 = a4 > 0.f ? a4 : 0.01f * a4;
        acc[0] += a0 * zs.x;  acc[1] += a0 * zs.y;
        acc[2] += a1 * zs.x;  acc[3] += a1 * zs.y;
        acc[4] += a2 * zs.x;  acc[5] += a2 * zs.y;
        acc[6] += a3 * zs.x;  acc[7] += a3 * zs.y;
        acc[8] += a4 * zs.x;  acc[9] += a4 * zs.y;
    }

    float* ob = out + (long)d_cur * OUTC + 2 * lane;
#pragma unroll
    for (int h = 0; h < NHEADS; h++)
        asm volatile("red.global.add.v2.f32 [%0], {%1, %2};"
                     :: "l"(ob + h * F), "f"(acc[2 * h]), "f"(acc[2 * h + 1])
                     : "memory");
}

// ---------------------------------------------------------------------------
extern "C" void kernel_launch(void* const* d_in, const int* in_sizes, int n_in,
                              void* d_out, int out_size)
{
    const float* feat      = (const float*)d_in[0];
    const int*   src       = (const int*)  d_in[1];
    const int*   dst       = (const int*)  d_in[2];
    const int*   etype     = (const int*)  d_in[3];
    const float* fc_w      = (const float*)d_in[4];
    const float* self_fc_w = (const float*)d_in[5];
    const float* aw        = (const float*)d_in[6];
    const float* w_comp    = (const float*)d_in[7];
    float* out = (float*)d_out;

    const int NB = (N_NODES + 1023) / 1024;   // 25

    static cudaStream_t s_side = nullptr;
    static cudaEvent_t  ev_fork = nullptr, ev_sort = nullptr;
    if (s_side == nullptr) {
        cudaStreamCreateWithFlags(&s_side, cudaStreamNonBlocking);
        cudaEventCreateWithFlags(&ev_fork, cudaEventDisableTiming);
        cudaEventCreateWithFlags(&ev_sort, cudaEventDisableTiming);
        cudaFuncSetAttribute(proj_mma_kernel,
                             cudaFuncAttributeMaxDynamicSharedMemorySize, PROJ_SMEM);
    }

    // ---- fork: sort chain on side stream
    cudaEventRecord(ev_fork, 0);
    cudaStreamWaitEvent(s_side, ev_fork, 0);
    hist_kernel<<<(N_EDGES / 4 + 255) / 256, 256, 0, s_side>>>(dst);     // launch 1

    // ---- main stream: weights -> projection GEMM (4th launch -> profiled)
    split_w_kernel<<<(WCOLS * KW + 255) / 256, 256>>>(fc_w, self_fc_w);  // launch 2
    attn_comp_kernel<<<NRELS, 320>>>(aw, w_comp, fc_w);                  // launch 3
    proj_mma_kernel<<<(N_NODES + 31) / 32, 256, PROJ_SMEM>>>(feat, out); // launch 4

    // ---- side stream: rest of sort chain
    scan1_kernel<<<NB, 1024, 0, s_side>>>();                             // launch 5
    scan3_kernel<<<NB, 1024, 0, s_side>>>();                             // launch 6
    scatter_kernel<<<(N_EDGES / 4 + 255) / 256, 256, 0, s_side>>>(dst, src, etype); // 7
    cudaEventRecord(ev_sort, s_side);

    // ---- join, then gather
    cudaStreamWaitEvent(0, ev_sort, 0);
    gather_kernel<<<(N_EDGES / CHUNK + 7) / 8, 256>>>(out);              // launch 8
}